// round 14
// baseline (speedup 1.0000x reference)
#include <cuda_runtime.h>

#define BB     32
#define NVV    6890
#define NFF    13776
#define MAXC   8
#define NCC    (NFF * MAXC)          // 110208
#define NPAIRS (BB * NCC)            // 3,526,656 = 13776 * 256 exactly
#define NREC   (BB * NFF)            // 440,832 records
#define SIGMA_F  0.5f
#define SIGMA2_F 0.25f
#define TPB    256
#define PAIRS_PER_BLOCK 256          // 8 warps * 4 octets * 8 iters
#define GRID_PAIR (NPAIRS / PAIRS_PER_BLOCK)   // 13776, exact

// 64B record per (b, face): {v0.xyz, cx}, {v1.xyz, cy}, {v2.xyz, cz}, {nx,ny,nz, 0}
// 64B-aligned -> exactly 2 L2 sectors per record. ~28.2 MB.
__device__ __align__(64) float4 g_recs[(size_t)NREC * 4];
__device__ double g_acc;
__device__ unsigned int g_cnt;

// ---------------------------------------------------------------------------
// Build: per (b, face) gather 3 verts, precompute centroid + normalized normal.
// ---------------------------------------------------------------------------
__global__ __launch_bounds__(256) void build_recs_kernel(
    const float* __restrict__ verts, const int* __restrict__ faces)
{
    int t = blockIdx.x * blockDim.x + threadIdx.x;
    if (t == 0) { g_acc = 0.0; g_cnt = 0u; }
    if (t >= NREC) return;
    int b = t / NFF;
    int f = t - b * NFF;
    int i0 = faces[3 * f + 0];
    int i1 = faces[3 * f + 1];
    int i2 = faces[3 * f + 2];
    const float* vb = verts + (size_t)b * NVV * 3;
    float v0x = vb[3*i0], v0y = vb[3*i0+1], v0z = vb[3*i0+2];
    float v1x = vb[3*i1], v1y = vb[3*i1+1], v1z = vb[3*i1+2];
    float v2x = vb[3*i2], v2y = vb[3*i2+1], v2z = vb[3*i2+2];

    const float third = 1.0f / 3.0f;
    float cx = (v0x + v1x + v2x) * third;
    float cy = (v0y + v1y + v2y) * third;
    float cz = (v0z + v1z + v2z) * third;

    float e1x = v1x - v0x, e1y = v1y - v0y, e1z = v1z - v0z;
    float e2x = v2x - v0x, e2y = v2y - v0y, e2z = v2z - v0z;
    float nx = e1y * e2z - e1z * e2y;
    float ny = e1z * e2x - e1x * e2z;
    float nz = e1x * e2y - e1y * e2x;
    float nn = sqrtf(fmaf(nx, nx, fmaf(ny, ny, nz * nz)));
    float inv = 1.0f / (nn + 1e-8f);
    nx *= inv; ny *= inv; nz *= inv;

    float4* dst = &g_recs[(size_t)t * 4];
    dst[0] = make_float4(v0x, v0y, v0z, cx);
    dst[1] = make_float4(v1x, v1y, v1z, cy);
    dst[2] = make_float4(v2x, v2y, v2z, cz);
    dst[3] = make_float4(nx,  ny,  nz,  0.0f);
}

// ---------------------------------------------------------------------------
// Pair kernel, OCTET-per-pair. Lanes m=0..3 of each octet load float4 m of
// record A; lanes 4..7 load float4 m-4 of record I (one warp LDG touches 8
// records = 8 lines = 2 wavefronts/pair, full 64B payload used).
// Exchange: 6 shfl.idx (width 8) with per-lane sources serve BOTH directions
// at once (1.5 shfl-instr/pair): lanes 0-2 get I's centroid+normal and
// evaluate their local A-vertex in I's field (dir 2); lanes 4-6 get A's field
// and evaluate their I-vertex (dir 1). Lanes 3,7 are normal-carriers only.
// MIO ops/pair: 2 wf + 1.5 shfl + 0.25 cidx  (was ~5.6 in quad scheme).
// ---------------------------------------------------------------------------
__global__ __launch_bounds__(TPB) void pair_kernel(
    const int2* __restrict__ cidx,
    const float* __restrict__ weight,
    float* __restrict__ out)
{
    __shared__ float s_wsum[TPB / 32];

    const unsigned FULL = 0xffffffffu;
    int tid  = threadIdx.x;
    int lane = tid & 31;
    int w    = tid >> 5;
    int oct  = lane >> 3;        // 0..3
    int m    = lane & 7;         // 0..7 within octet
    int lm   = m & 3;            // float4 index within record
    bool sideA = (m < 4);

    float pen = 0.0f;

    #pragma unroll
    for (int it = 0; it < 8; ++it) {
        int p = blockIdx.x * PAIRS_PER_BLOCK + it * 32 + w * 4 + oct;
        int2 ids = cidx[p];                    // 8 lanes same addr -> bcast
        bool valid = ids.x >= 0;
        int  b  = p / NCC;
        int  rb = b * NFF;
        int  ra = rb + (valid ? ids.x : 0);
        int  ri = rb + max(ids.y, 0);

        int  base = sideA ? ra : ri;
        float4 f = __ldg(&g_recs[(size_t)base * 4 + lm]);

        // Cross-side broadcasts (width-8 shfl, per-lane source):
        // A-side lanes fetch I's field; I-side lanes fetch A's field.
        int cs = sideA ? 4 : 0;
        int ns = sideA ? 7 : 3;
        float cx = __shfl_sync(FULL, f.w, cs + 0, 8);
        float cy = __shfl_sync(FULL, f.w, cs + 1, 8);
        float cz = __shfl_sync(FULL, f.w, cs + 2, 8);
        float nx = __shfl_sync(FULL, f.x, ns, 8);
        float ny = __shfl_sync(FULL, f.y, ns, 8);
        float nz = __shfl_sync(FULL, f.z, ns, 8);

        // Lane lm<3 evaluates its local vertex in the OTHER record's field.
        if (valid && lm < 3) {
            float dx = f.x - cx, dy = f.y - cy, dz = f.z - cz;
            float r2 = fmaf(dx, dx, fmaf(dy, dy, dz * dz));
            if (r2 < SIGMA2_F) {
                float h = fmaf(dx, nx, fmaf(dy, ny, dz * nz));
                if (h < 0.0f) pen = fmaf((SIGMA_F - sqrtf(r2)) * h, h, pen);
            }
        }
    }

    // warp reduce: every lane's contribution summed exactly once
    #pragma unroll
    for (int o = 16; o > 0; o >>= 1)
        pen += __shfl_down_sync(FULL, pen, o);
    if (lane == 0) s_wsum[w] = pen;
    __syncthreads();
    if (w == 0) {
        float v = (lane < TPB / 32) ? s_wsum[lane] : 0.0f;
        #pragma unroll
        for (int o = 4; o > 0; o >>= 1)
            v += __shfl_down_sync(0xffu, v, o);
        if (lane == 0) {
            atomicAdd(&g_acc, (double)v);
            __threadfence();
            unsigned int done = atomicAdd(&g_cnt, 1u);
            if (done == (unsigned int)(GRID_PAIR - 1)) {
                double total = atomicAdd(&g_acc, 0.0);
                out[0] = (float)(total * (1.0 / (double)BB)) * weight[0];
            }
        }
    }
}

extern "C" void kernel_launch(void* const* d_in, const int* in_sizes, int n_in,
                              void* d_out, int out_size)
{
    // metadata order: pose, joints, points, keypoints, vertices, weight, faces, collision_idxs
    const float* vertices = (const float*)d_in[4];
    const float* weight   = (const float*)d_in[5];
    const int*   faces    = (const int*)d_in[6];
    const int2*  cidx     = (const int2*)d_in[7];

    build_recs_kernel<<<(NREC + 255) / 256, 256>>>(vertices, faces);
    pair_kernel<<<GRID_PAIR, TPB>>>(cidx, weight, (float*)d_out);
}

// round 16
// speedup vs baseline: 1.2600x; 1.2600x over previous
#include <cuda_runtime.h>

#define BB     32
#define NVV    6890
#define NFF    13776
#define MAXC   8
#define NCC    (NFF * MAXC)          // 110208
#define NPAIRS (BB * NCC)            // 3,526,656 = 13776 * 256 exactly
#define NREC   (BB * NFF)            // 440,832 records
#define SIGMA_F  0.5f
#define SIGMA2_F 0.25f
#define TPB    256
#define PAIRS_PER_BLOCK 256          // 8 warps * 8 quads * 4 iters
#define GRID_PAIR (NPAIRS / PAIRS_PER_BLOCK)   // 13776, exact

// 64B record per (b, face): {v0.xyz, cx}, {v1.xyz, cy}, {v2.xyz, cz}, {nx,ny,nz, 0}
__device__ __align__(64) float4 g_recs[(size_t)NREC * 4];
__device__ double g_acc;
__device__ unsigned int g_cnt;

// ---------------------------------------------------------------------------
// Build: per (b, face) gather 3 verts, precompute centroid + normalized normal.
// ---------------------------------------------------------------------------
__global__ __launch_bounds__(256) void build_recs_kernel(
    const float* __restrict__ verts, const int* __restrict__ faces)
{
    int t = blockIdx.x * blockDim.x + threadIdx.x;
    if (t == 0) { g_acc = 0.0; g_cnt = 0u; }
    if (t >= NREC) return;
    int b = t / NFF;
    int f = t - b * NFF;
    int i0 = faces[3 * f + 0];
    int i1 = faces[3 * f + 1];
    int i2 = faces[3 * f + 2];
    const float* vb = verts + (size_t)b * NVV * 3;
    float v0x = vb[3*i0], v0y = vb[3*i0+1], v0z = vb[3*i0+2];
    float v1x = vb[3*i1], v1y = vb[3*i1+1], v1z = vb[3*i1+2];
    float v2x = vb[3*i2], v2y = vb[3*i2+1], v2z = vb[3*i2+2];

    const float third = 1.0f / 3.0f;
    float cx = (v0x + v1x + v2x) * third;
    float cy = (v0y + v1y + v2y) * third;
    float cz = (v0z + v1z + v2z) * third;

    float e1x = v1x - v0x, e1y = v1y - v0y, e1z = v1z - v0z;
    float e2x = v2x - v0x, e2y = v2y - v0y, e2z = v2z - v0z;
    float nx = e1y * e2z - e1z * e2y;
    float ny = e1z * e2x - e1x * e2z;
    float nz = e1x * e2y - e1y * e2x;
    float nn = sqrtf(fmaf(nx, nx, fmaf(ny, ny, nz * nz)));
    float inv = 1.0f / (nn + 1e-8f);
    nx *= inv; ny *= inv; nz *= inv;

    float4* dst = &g_recs[(size_t)t * 4];
    dst[0] = make_float4(v0x, v0y, v0z, cx);
    dst[1] = make_float4(v1x, v1y, v1z, cy);
    dst[2] = make_float4(v2x, v2y, v2z, cz);
    dst[3] = make_float4(nx,  ny,  nz,  0.0f);
}

// ---------------------------------------------------------------------------
// Pair kernel, quad-per-pair (R13 structure, measured 67.5us) + manual 2-stage
// software pipeline: iteration it+1's cidx + record loads are issued BEFORE
// the shuffle/eval block of iteration it, hiding L2 (~230cyc) and SHFL (~26cyc)
// latency under MIO/FMA work. Constant-source width-4 shuffles only.
// ---------------------------------------------------------------------------
__global__ __launch_bounds__(TPB) void pair_kernel(
    const int2* __restrict__ cidx,
    const float* __restrict__ weight,
    float* __restrict__ out)
{
    __shared__ float s_wsum[TPB / 32];

    const unsigned FULL = 0xffffffffu;
    int tid  = threadIdx.x;
    int lane = tid & 31;
    int w    = tid >> 5;
    int quad = lane >> 2;
    int lc   = lane & 3;

    int pbase = blockIdx.x * PAIRS_PER_BLOCK + w * 8 + quad;

    float pen = 0.0f;

    // ---- prologue: stage iteration 0 ----
    int2  ids = __ldg(&cidx[pbase]);
    float4 fA, fI;
    {
        bool v = ids.x >= 0;
        int  b  = pbase / NCC;
        int  rb = b * NFF;
        fA = __ldg(&g_recs[(size_t)(rb + (v ? ids.x : 0)) * 4 + lc]);
        fI = __ldg(&g_recs[(size_t)(rb + max(ids.y, 0)) * 4 + lc]);
    }

    #pragma unroll
    for (int it = 0; it < 4; ++it) {
        // ---- prefetch iteration it+1 (issued before current eval) ----
        int2  nids;
        float4 nfA, nfI;
        if (it < 3) {
            int np = pbase + (it + 1) * 64;
            nids = __ldg(&cidx[np]);
            bool v = nids.x >= 0;
            int  b  = np / NCC;
            int  rb = b * NFF;
            nfA = __ldg(&g_recs[(size_t)(rb + (v ? nids.x : 0)) * 4 + lc]);
            nfI = __ldg(&g_recs[(size_t)(rb + max(nids.y, 0)) * 4 + lc]);
        }

        // ---- current iteration: exchange + eval ----
        bool valid = ids.x >= 0;

        float cAx = __shfl_sync(FULL, fA.w, 0, 4);
        float cAy = __shfl_sync(FULL, fA.w, 1, 4);
        float cAz = __shfl_sync(FULL, fA.w, 2, 4);
        float nAx = __shfl_sync(FULL, fA.x, 3, 4);
        float nAy = __shfl_sync(FULL, fA.y, 3, 4);
        float nAz = __shfl_sync(FULL, fA.z, 3, 4);
        float cIx = __shfl_sync(FULL, fI.w, 0, 4);
        float cIy = __shfl_sync(FULL, fI.w, 1, 4);
        float cIz = __shfl_sync(FULL, fI.w, 2, 4);
        float nIx = __shfl_sync(FULL, fI.x, 3, 4);
        float nIy = __shfl_sync(FULL, fI.y, 3, 4);
        float nIz = __shfl_sync(FULL, fI.z, 3, 4);

        if (valid && lc < 3) {
            // direction 1: my I vertex inside A's cone field
            float dx = fI.x - cAx, dy = fI.y - cAy, dz = fI.z - cAz;
            float r2 = fmaf(dx, dx, fmaf(dy, dy, dz * dz));
            if (r2 < SIGMA2_F) {
                float h = fmaf(dx, nAx, fmaf(dy, nAy, dz * nAz));
                if (h < 0.0f) pen = fmaf((SIGMA_F - sqrtf(r2)) * h, h, pen);
            }
            // direction 2: my A vertex inside I's cone field
            float ex = fA.x - cIx, ey = fA.y - cIy, ez = fA.z - cIz;
            float s2 = fmaf(ex, ex, fmaf(ey, ey, ez * ez));
            if (s2 < SIGMA2_F) {
                float g = fmaf(ex, nIx, fmaf(ey, nIy, ez * nIz));
                if (g < 0.0f) pen = fmaf((SIGMA_F - sqrtf(s2)) * g, g, pen);
            }
        }

        // ---- rotate pipeline ----
        if (it < 3) { ids = nids; fA = nfA; fI = nfI; }
    }

    // warp reduce: every lane's contribution summed exactly once
    #pragma unroll
    for (int o = 16; o > 0; o >>= 1)
        pen += __shfl_down_sync(FULL, pen, o);
    if (lane == 0) s_wsum[w] = pen;
    __syncthreads();
    if (w == 0) {
        float v = (lane < TPB / 32) ? s_wsum[lane] : 0.0f;
        #pragma unroll
        for (int o = 4; o > 0; o >>= 1)
            v += __shfl_down_sync(0xffu, v, o);
        if (lane == 0) {
            atomicAdd(&g_acc, (double)v);
            __threadfence();
            unsigned int done = atomicAdd(&g_cnt, 1u);
            if (done == (unsigned int)(GRID_PAIR - 1)) {
                double total = atomicAdd(&g_acc, 0.0);
                out[0] = (float)(total * (1.0 / (double)BB)) * weight[0];
            }
        }
    }
}

extern "C" void kernel_launch(void* const* d_in, const int* in_sizes, int n_in,
                              void* d_out, int out_size)
{
    // metadata order: pose, joints, points, keypoints, vertices, weight, faces, collision_idxs
    const float* vertices = (const float*)d_in[4];
    const float* weight   = (const float*)d_in[5];
    const int*   faces    = (const int*)d_in[6];
    const int2*  cidx     = (const int2*)d_in[7];

    build_recs_kernel<<<(NREC + 255) / 256, 256>>>(vertices, faces);
    pair_kernel<<<GRID_PAIR, TPB>>>(cidx, weight, (float*)d_out);
}

// round 17
// speedup vs baseline: 1.3756x; 1.0917x over previous
#include <cuda_runtime.h>

#define BB     32
#define NVV    6890
#define NFF    13776
#define MAXC   8
#define NCC    (NFF * MAXC)          // 110208
#define NPAIRS (BB * NCC)            // 3,526,656 = 13776 * 256 exactly
#define NREC   (BB * NFF)            // 440,832 records
#define SIGMA_F  0.5f
#define SIGMA2_F 0.25f
#define TPB    256
#define PAIRS_PER_BLOCK 256          // 8 warps * 8 quads * 4 iters
#define GRID_PAIR (NPAIRS / PAIRS_PER_BLOCK)   // 13776, exact

// 64B record per (b, face): {v0.xyz, cx}, {v1.xyz, cy}, {v2.xyz, cz}, {nx,ny,nz, 0}
__device__ __align__(64) float4 g_recs[(size_t)NREC * 4];
__device__ double g_acc;
__device__ unsigned int g_cnt;

// ---------------------------------------------------------------------------
// Build: per (b, face) gather 3 verts, precompute centroid + normalized normal.
// ---------------------------------------------------------------------------
__global__ __launch_bounds__(256) void build_recs_kernel(
    const float* __restrict__ verts, const int* __restrict__ faces)
{
    int t = blockIdx.x * blockDim.x + threadIdx.x;
    if (t == 0) { g_acc = 0.0; g_cnt = 0u; }
    if (t >= NREC) return;
    int b = t / NFF;
    int f = t - b * NFF;
    int i0 = faces[3 * f + 0];
    int i1 = faces[3 * f + 1];
    int i2 = faces[3 * f + 2];
    const float* vb = verts + (size_t)b * NVV * 3;
    float v0x = vb[3*i0], v0y = vb[3*i0+1], v0z = vb[3*i0+2];
    float v1x = vb[3*i1], v1y = vb[3*i1+1], v1z = vb[3*i1+2];
    float v2x = vb[3*i2], v2y = vb[3*i2+1], v2z = vb[3*i2+2];

    const float third = 1.0f / 3.0f;
    float cx = (v0x + v1x + v2x) * third;
    float cy = (v0y + v1y + v2y) * third;
    float cz = (v0z + v1z + v2z) * third;

    float e1x = v1x - v0x, e1y = v1y - v0y, e1z = v1z - v0z;
    float e2x = v2x - v0x, e2y = v2y - v0y, e2z = v2z - v0z;
    float nx = e1y * e2z - e1z * e2y;
    float ny = e1z * e2x - e1x * e2z;
    float nz = e1x * e2y - e1y * e2x;
    float nn = sqrtf(fmaf(nx, nx, fmaf(ny, ny, nz * nz)));
    float inv = 1.0f / (nn + 1e-8f);
    nx *= inv; ny *= inv; nz *= inv;

    float4* dst = &g_recs[(size_t)t * 4];
    dst[0] = make_float4(v0x, v0y, v0z, cx);
    dst[1] = make_float4(v1x, v1y, v1z, cy);
    dst[2] = make_float4(v2x, v2y, v2z, cz);
    dst[3] = make_float4(nx,  ny,  nz,  0.0f);
}

// ---------------------------------------------------------------------------
// Pair kernel, quad-per-pair (R13 structure, measured 67.5us) + warp-level
// early-out: centroid shuffles + r^2 tests FIRST (zero added FLOPs -- first
// half of eval hoisted), then one VOTE.ANY; ~34% of warp-iters have no vertex
// with r^2 < sigma^2 anywhere in the warp and skip the 6 normal shuffles +
// h/pen block entirely.
// ---------------------------------------------------------------------------
__global__ __launch_bounds__(TPB) void pair_kernel(
    const int2* __restrict__ cidx,
    const float* __restrict__ weight,
    float* __restrict__ out)
{
    __shared__ float s_wsum[TPB / 32];

    const unsigned FULL = 0xffffffffu;
    int tid  = threadIdx.x;
    int lane = tid & 31;
    int w    = tid >> 5;
    int quad = lane >> 2;
    int lc   = lane & 3;

    float pen = 0.0f;

    #pragma unroll
    for (int it = 0; it < 4; ++it) {
        int p = blockIdx.x * PAIRS_PER_BLOCK + it * 64 + w * 8 + quad;
        int2 ids = cidx[p];                       // 4 lanes/quad same addr -> bcast
        bool valid = ids.x >= 0;
        int  b  = p / NCC;
        int  rb = b * NFF;
        int  ra = rb + (valid ? ids.x : 0);
        int  ri = rb + max(ids.y, 0);

        float4 fA = __ldg(&g_recs[(size_t)ra * 4 + lc]);
        float4 fI = __ldg(&g_recs[(size_t)ri * 4 + lc]);

        // --- centroid broadcasts (6 shfl) + r^2 tests (hoisted eval half) ---
        float cAx = __shfl_sync(FULL, fA.w, 0, 4);
        float cAy = __shfl_sync(FULL, fA.w, 1, 4);
        float cAz = __shfl_sync(FULL, fA.w, 2, 4);
        float cIx = __shfl_sync(FULL, fI.w, 0, 4);
        float cIy = __shfl_sync(FULL, fI.w, 1, 4);
        float cIz = __shfl_sync(FULL, fI.w, 2, 4);

        // dir 1: my I vertex vs A's centroid;  dir 2: my A vertex vs I's centroid
        float d1x = fI.x - cAx, d1y = fI.y - cAy, d1z = fI.z - cAz;
        float r21 = fmaf(d1x, d1x, fmaf(d1y, d1y, d1z * d1z));
        float d2x = fA.x - cIx, d2y = fA.y - cIy, d2z = fA.z - cIz;
        float r22 = fmaf(d2x, d2x, fmaf(d2y, d2y, d2z * d2z));

        bool alive = valid && (lc < 3) && (fminf(r21, r22) < SIGMA2_F);
        if (!__any_sync(FULL, alive)) continue;   // whole warp dead: skip 6 shfl + eval

        // --- normal broadcasts (6 shfl) + h tests + accumulation ---
        float nAx = __shfl_sync(FULL, fA.x, 3, 4);
        float nAy = __shfl_sync(FULL, fA.y, 3, 4);
        float nAz = __shfl_sync(FULL, fA.z, 3, 4);
        float nIx = __shfl_sync(FULL, fI.x, 3, 4);
        float nIy = __shfl_sync(FULL, fI.y, 3, 4);
        float nIz = __shfl_sync(FULL, fI.z, 3, 4);

        if (valid && lc < 3) {
            if (r21 < SIGMA2_F) {
                float h = fmaf(d1x, nAx, fmaf(d1y, nAy, d1z * nAz));
                if (h < 0.0f) pen = fmaf((SIGMA_F - sqrtf(r21)) * h, h, pen);
            }
            if (r22 < SIGMA2_F) {
                float g = fmaf(d2x, nIx, fmaf(d2y, nIy, d2z * nIz));
                if (g < 0.0f) pen = fmaf((SIGMA_F - sqrtf(r22)) * g, g, pen);
            }
        }
    }

    // warp reduce: every lane's contribution summed exactly once
    #pragma unroll
    for (int o = 16; o > 0; o >>= 1)
        pen += __shfl_down_sync(FULL, pen, o);
    if (lane == 0) s_wsum[w] = pen;
    __syncthreads();
    if (w == 0) {
        float v = (lane < TPB / 32) ? s_wsum[lane] : 0.0f;
        #pragma unroll
        for (int o = 4; o > 0; o >>= 1)
            v += __shfl_down_sync(0xffu, v, o);
        if (lane == 0) {
            atomicAdd(&g_acc, (double)v);
            __threadfence();
            unsigned int done = atomicAdd(&g_cnt, 1u);
            if (done == (unsigned int)(GRID_PAIR - 1)) {
                double total = atomicAdd(&g_acc, 0.0);
                out[0] = (float)(total * (1.0 / (double)BB)) * weight[0];
            }
        }
    }
}

extern "C" void kernel_launch(void* const* d_in, const int* in_sizes, int n_in,
                              void* d_out, int out_size)
{
    // metadata order: pose, joints, points, keypoints, vertices, weight, faces, collision_idxs
    const float* vertices = (const float*)d_in[4];
    const float* weight   = (const float*)d_in[5];
    const int*   faces    = (const int*)d_in[6];
    const int2*  cidx     = (const int2*)d_in[7];

    build_recs_kernel<<<(NREC + 255) / 256, 256>>>(vertices, faces);
    pair_kernel<<<GRID_PAIR, TPB>>>(cidx, weight, (float*)d_out);
}